// round 3
// baseline (speedup 1.0000x reference)
#include <cuda_runtime.h>
#include <cuda_bf16.h>
#include <cstdint>

// ConvPooler — per-token dot(h[b,s,:], w) + bias scattered into
// out[b, gene_pos[b,s]] over a [B, 60000] zeroed buffer; pad id 60000 dropped.
// B=32, S=2048, D=512, FULL_SEQ_LEN=60000. gene_pos is int32.

#define B_DIM 32
#define S_DIM 2048
#define D_DIM 512
#define FULL_SEQ 60000

// ---------------------------------------------------------------------------
// Kernel 1: zero the output buffer. Exact-fit grid, one float4 per thread.
// out_size = 1,920,000 floats = 480,000 float4 = 1875 blocks * 256 threads.
// ---------------------------------------------------------------------------
__global__ void zero_out_kernel(float4* __restrict__ out, int n4) {
    int i = blockIdx.x * blockDim.x + threadIdx.x;
    if (i < n4) out[i] = make_float4(0.f, 0.f, 0.f, 0.f);
}

// ---------------------------------------------------------------------------
// Kernel 2: TWO tokens per warp. Each lane fronts 8 independent float4 loads
// (4 from each of 2 adjacent token rows) -> MLP=8/thread to saturate HBM.
// Butterfly-reduce both accumulators; lanes 0 and 1 scatter in parallel.
// ---------------------------------------------------------------------------
__global__ __launch_bounds__(256, 6)
void conv_scatter_kernel(const float4* __restrict__ h,        // [B*S, D/4]
                         const int* __restrict__ gene_pos,    // [B*S] int32
                         const float4* __restrict__ w,        // [D/4]
                         const float* __restrict__ bias,      // [1]
                         float* __restrict__ out) {           // [B, FULL_SEQ]
    const int warp_id = (blockIdx.x * blockDim.x + threadIdx.x) >> 5;
    const int lane    = threadIdx.x & 31;

    const int t0 = warp_id * 2;            // first token of this warp's pair
    // n_tok = 65536; grid exactly covers 32768 warps — no bounds check needed,
    // but keep a cheap guard for safety.
    if (t0 >= B_DIM * S_DIM) return;

    const float4* r0 = h + (size_t)t0 * (D_DIM / 4);
    const float4* r1 = r0 + (D_DIM / 4);

    float acc0 = 0.f, acc1 = 0.f;
#pragma unroll
    for (int j = 0; j < 4; ++j) {
        const int idx = lane + 32 * j;
        float4 a = r0[idx];                // independent loads: compiler
        float4 c = r1[idx];                // front-batches 8 LDG.128 + 4 w
        float4 wv = __ldg(&w[idx]);
        acc0 = fmaf(a.x, wv.x, acc0);
        acc0 = fmaf(a.y, wv.y, acc0);
        acc0 = fmaf(a.z, wv.z, acc0);
        acc0 = fmaf(a.w, wv.w, acc0);
        acc1 = fmaf(c.x, wv.x, acc1);
        acc1 = fmaf(c.y, wv.y, acc1);
        acc1 = fmaf(c.z, wv.z, acc1);
        acc1 = fmaf(c.w, wv.w, acc1);
    }

    // butterfly reductions (results broadcast to all lanes)
#pragma unroll
    for (int off = 16; off > 0; off >>= 1) {
        acc0 += __shfl_xor_sync(0xFFFFFFFFu, acc0, off);
        acc1 += __shfl_xor_sync(0xFFFFFFFFu, acc1, off);
    }

    // lanes 0 and 1 scatter their token (same batch row: S even)
    if (lane < 2) {
        const int tok = t0 + lane;
        const int gp  = gene_pos[tok];
        if (gp >= 0 && gp < FULL_SEQ) {
            const int row = tok >> 11;     // tok / S_DIM
            const float v = (lane == 0 ? acc0 : acc1) + bias[0];
            out[(size_t)row * FULL_SEQ + (size_t)gp] = v;
        }
    }
}

// ---------------------------------------------------------------------------
// Launch — map inputs by element count (robust to metadata ordering):
// h=33554432, gene_pos=65536, w=512, b=1.
// ---------------------------------------------------------------------------
extern "C" void kernel_launch(void* const* d_in, const int* in_sizes, int n_in,
                              void* d_out, int out_size) {
    const void* h_p = nullptr;
    const void* gp_p = nullptr;
    const void* w_p = nullptr;
    const void* b_p = nullptr;
    for (int i = 0; i < n_in; ++i) {
        switch (in_sizes[i]) {
            case B_DIM * S_DIM * D_DIM: h_p  = d_in[i]; break;  // 33,554,432
            case B_DIM * S_DIM:         gp_p = d_in[i]; break;  // 65,536
            case D_DIM:                 w_p  = d_in[i]; break;  // 512
            case 1:                     b_p  = d_in[i]; break;
            default: break;
        }
    }

    const float* h  = (const float*)h_p;
    const int*   gp = (const int*)gp_p;
    const float* w  = (const float*)w_p;
    const float* b  = (const float*)b_p;
    float* out = (float*)d_out;

    // Zero the output: 480,000 float4 stores, exact-fit grid.
    const int n4 = out_size / 4;
    const int zt = 256;
    const int zb = (n4 + zt - 1) / zt;     // 1875
    zero_out_kernel<<<zb, zt>>>((float4*)out, n4);

    // 2 tokens/warp: 32768 warps, 8 warps/block -> 4096 blocks.
    const int n_tok   = B_DIM * S_DIM;
    const int threads = 256;
    const int blocks  = (n_tok / 2 * 32) / threads;  // 4096
    conv_scatter_kernel<<<blocks, threads>>>(
        (const float4*)h, gp, (const float4*)w, b, out);
}